// round 5
// baseline (speedup 1.0000x reference)
#include <cuda_runtime.h>
#include <cuda_bf16.h>
#include <math.h>

// ---------------- constants ----------------
#define LAYERS 12
#define HEADS  12
#define EMB    768
#define DHEAD  64
#define VOCAB  50257
#define BATCH  4
#define SEQ    1024
#define TOK    (BATCH * SEQ)          // 4096
#define E3     (3 * EMB)              // 2304
#define E4     (4 * EMB)              // 3072

// ---------------- scratch (__device__ globals: no cudaMalloc allowed) ------
__device__ float g_h  [(size_t)TOK * EMB];            // residual stream
__device__ float g_a  [(size_t)TOK * EMB];            // layernorm output
__device__ float g_y  [(size_t)TOK * EMB];            // attention output
__device__ float g_qkv[(size_t)TOK * E3];             // qkv projections
__device__ float g_att[(size_t)BATCH * HEADS * SEQ * SEQ]; // attn probs
__device__ float g_fc [(size_t)TOK * E4];             // MLP hidden

// ---------------- helpers ----------------
__device__ __forceinline__ float gelu_f(float x) {
    float x3 = x * x * x;
    return 0.5f * x * (1.0f + tanhf(0.7978845608028654f * (x + 0.044715f * x3)));
}

__device__ __forceinline__ float warp_sum(float v) {
    #pragma unroll
    for (int o = 16; o > 0; o >>= 1) v += __shfl_xor_sync(0xffffffffu, v, o);
    return v;
}
__device__ __forceinline__ float warp_max(float v) {
    #pragma unroll
    for (int o = 16; o > 0; o >>= 1) v = fmaxf(v, __shfl_xor_sync(0xffffffffu, v, o));
    return v;
}
// block-wide reductions for 256 threads (8 warps); sm must hold >=8 floats
__device__ __forceinline__ float block_sum(float v, float* sm) {
    v = warp_sum(v);
    int w = threadIdx.x >> 5, l = threadIdx.x & 31;
    if (l == 0) sm[w] = v;
    __syncthreads();
    float r = (l < 8) ? sm[l] : 0.0f;
    r = warp_sum(r);
    __syncthreads();
    return r;
}
__device__ __forceinline__ float block_max(float v, float* sm) {
    v = warp_max(v);
    int w = threadIdx.x >> 5, l = threadIdx.x & 31;
    if (l == 0) sm[w] = v;
    __syncthreads();
    float r = (l < 8) ? sm[l] : -3.0e38f;
    r = warp_max(r);
    __syncthreads();
    return r;
}

// ---------------- embedding ----------------
__global__ __launch_bounds__(256) void embed_kernel(
    const int* __restrict__ x, const float* __restrict__ wte,
    const float* __restrict__ wpe, float* __restrict__ h)
{
    int i = blockIdx.x * 256 + threadIdx.x;
    if (i < TOK * EMB) {
        int t = i / EMB;
        int e = i - t * EMB;
        int s = t & (SEQ - 1);
        h[i] = wte[(size_t)x[t] * EMB + e] + wpe[(size_t)s * EMB + e];
    }
}

// ---------------- layernorm (row = 768) ----------------
__global__ __launch_bounds__(256) void ln_kernel(
    const float* __restrict__ x, const float* __restrict__ g,
    const float* __restrict__ b, float* __restrict__ y)
{
    __shared__ float red[8];
    int row = blockIdx.x;
    const float* xr = x + (size_t)row * EMB;
    int tid = threadIdx.x;
    float v0 = xr[tid], v1 = xr[tid + 256], v2 = xr[tid + 512];
    float s  = v0 + v1 + v2;
    float s2 = v0 * v0 + v1 * v1 + v2 * v2;
    s  = block_sum(s,  red);
    __syncthreads();
    s2 = block_sum(s2, red);
    float mean = s * (1.0f / EMB);
    float var  = s2 * (1.0f / EMB) - mean * mean;
    float inv  = rsqrtf(var + 1e-5f);
    float* yr = y + (size_t)row * EMB;
    yr[tid]       = (v0 - mean) * inv * g[tid]       + b[tid];
    yr[tid + 256] = (v1 - mean) * inv * g[tid + 256] + b[tid + 256];
    yr[tid + 512] = (v2 - mean) * inv * g[tid + 512] + b[tid + 512];
}

// ---------------- SGEMM: C[M,N] = A[M,K] @ B[K,N] (+bias) ----------------
// EPI: 0 = write, 1 = gelu then write, 2 = accumulate into C (residual)
// M always divisible by 128, K divisible by 8. N may be ragged AND may have
// an odd row stride (lm head: N=50257) -> float4 B loads only when
// (N % 4 == 0) AND the block's columns are fully in-bounds.
template <int EPI>
__global__ __launch_bounds__(256) void sgemm_kernel(
    const float* __restrict__ A, const float* __restrict__ B,
    const float* __restrict__ bias, float* __restrict__ C,
    int M, int N, int K)
{
    __shared__ float As[8][128];
    __shared__ float Bs[8][128];

    int tid = threadIdx.x;
    int bm = blockIdx.y * 128;
    int bn = blockIdx.x * 128;

    int arow = tid >> 1;            // 0..127
    int acol = (tid & 1) * 4;       // 0 or 4
    int brow = tid >> 5;            // 0..7
    int bcol = (tid & 31) * 4;      // 0..124

    int tr = (tid >> 4) * 8;        // 0..120
    int tc = (tid & 15) * 8;        // 0..120

    float acc[8][8];
    #pragma unroll
    for (int i = 0; i < 8; i++)
        #pragma unroll
        for (int j = 0; j < 8; j++) acc[i][j] = 0.0f;

    const float* Aptr = A + (size_t)(bm + arow) * K + acol;
    // vectorized B loads require: block fully in-bounds AND 16B-aligned rows
    bool bvec = ((bn + 128) <= N) && ((N & 3) == 0);

    for (int k0 = 0; k0 < K; k0 += 8) {
        float4 av = *(const float4*)(Aptr + k0);
        As[acol + 0][arow] = av.x;
        As[acol + 1][arow] = av.y;
        As[acol + 2][arow] = av.z;
        As[acol + 3][arow] = av.w;
        if (bvec) {
            float4 bv = *(const float4*)(B + (size_t)(k0 + brow) * N + bn + bcol);
            *(float4*)&Bs[brow][bcol] = bv;
        } else {
            const float* Brow = B + (size_t)(k0 + brow) * N;
            #pragma unroll
            for (int j = 0; j < 4; j++) {
                int n = bn + bcol + j;
                Bs[brow][bcol + j] = (n < N) ? Brow[n] : 0.0f;
            }
        }
        __syncthreads();
        #pragma unroll
        for (int kk = 0; kk < 8; kk++) {
            float4 a0 = *(const float4*)&As[kk][tr];
            float4 a1 = *(const float4*)&As[kk][tr + 4];
            float4 b0 = *(const float4*)&Bs[kk][tc];
            float4 b1 = *(const float4*)&Bs[kk][tc + 4];
            float ra[8] = {a0.x, a0.y, a0.z, a0.w, a1.x, a1.y, a1.z, a1.w};
            float rb[8] = {b0.x, b0.y, b0.z, b0.w, b1.x, b1.y, b1.z, b1.w};
            #pragma unroll
            for (int i = 0; i < 8; i++)
                #pragma unroll
                for (int j = 0; j < 8; j++)
                    acc[i][j] += ra[i] * rb[j];
        }
        __syncthreads();
    }

    #pragma unroll
    for (int i = 0; i < 8; i++) {
        size_t row = (size_t)(bm + tr + i);
        #pragma unroll
        for (int j = 0; j < 8; j++) {
            int n = bn + tc + j;
            if (n < N) {
                float v = acc[i][j];
                if (bias) v += bias[n];
                size_t idx = row * (size_t)N + n;
                if (EPI == 1) v = gelu_f(v);
                if (EPI == 2) v += C[idx];
                C[idx] = v;
            }
        }
    }
}

// ---------------- attention: scores = Q K^T * scale (64x64 tiles) --------
__global__ __launch_bounds__(256) void qk_kernel(
    const float* __restrict__ qkv, float* __restrict__ att)
{
    int kt = blockIdx.x, qt = blockIdx.y, bh = blockIdx.z;
    if (kt > qt) return;             // fully-masked tile
    int b = bh / HEADS, h = bh - b * HEADS;

    __shared__ float Qt[64][68];     // [d][q]
    __shared__ float Kt[64][68];     // [d][k]
    int tid = threadIdx.x;

    const float* qb = qkv + (size_t)(b * SEQ + qt * 64) * E3 + h * DHEAD;
    const float* kb = qkv + (size_t)(b * SEQ + kt * 64) * E3 + EMB + h * DHEAD;

    #pragma unroll
    for (int it = 0; it < 4; it++) {
        int lin = tid + 256 * it;    // 0..1023
        int r = lin >> 4;            // 0..63
        int d = (lin & 15) * 4;
        float4 qv = *(const float4*)(qb + (size_t)r * E3 + d);
        Qt[d + 0][r] = qv.x; Qt[d + 1][r] = qv.y;
        Qt[d + 2][r] = qv.z; Qt[d + 3][r] = qv.w;
        float4 kv = *(const float4*)(kb + (size_t)r * E3 + d);
        Kt[d + 0][r] = kv.x; Kt[d + 1][r] = kv.y;
        Kt[d + 2][r] = kv.z; Kt[d + 3][r] = kv.w;
    }
    __syncthreads();

    int tr = (tid >> 4) * 4;
    int tc = (tid & 15) * 4;
    float acc[4][4] = {};
    #pragma unroll
    for (int d = 0; d < 64; d++) {
        float4 qa = *(const float4*)&Qt[d][tr];
        float4 kk = *(const float4*)&Kt[d][tc];
        float ra[4] = {qa.x, qa.y, qa.z, qa.w};
        float rb[4] = {kk.x, kk.y, kk.z, kk.w};
        #pragma unroll
        for (int i = 0; i < 4; i++)
            #pragma unroll
            for (int j = 0; j < 4; j++)
                acc[i][j] += ra[i] * rb[j];
    }

    const float scale = 0.125f;      // 1/sqrt(64)
    float* out = att + ((size_t)bh * SEQ + qt * 64) * SEQ + kt * 64;
    #pragma unroll
    for (int i = 0; i < 4; i++)
        #pragma unroll
        for (int j = 0; j < 4; j++)
            out[(size_t)(tr + i) * SEQ + tc + j] = acc[i][j] * scale;
}

// ---------------- causal row softmax ----------------
__global__ __launch_bounds__(256) void softmax_kernel(float* __restrict__ att)
{
    __shared__ float red[8];
    int q = blockIdx.x, bh = blockIdx.y;
    float* row = att + ((size_t)bh * SEQ + q) * SEQ;
    int n = q + 1;
    int tid = threadIdx.x;

    float m = -3.0e38f;
    for (int j = tid; j < n; j += 256) m = fmaxf(m, row[j]);
    m = block_max(m, red);

    float s = 0.0f;
    for (int j = tid; j < n; j += 256) {
        float e = __expf(row[j] - m);
        row[j] = e;
        s += e;
    }
    s = block_sum(s, red);
    float inv = 1.0f / s;

    for (int j = tid; j < SEQ; j += 256)
        row[j] = (j < n) ? row[j] * inv : 0.0f;
}

// ---------------- attention: Y = P @ V (64x64 tiles over k) --------------
__global__ __launch_bounds__(256) void av_kernel(
    const float* __restrict__ att, const float* __restrict__ qkv,
    float* __restrict__ y)
{
    int qt = blockIdx.x, bh = blockIdx.y;
    int b = bh / HEADS, h = bh - b * HEADS;

    __shared__ float Pt[64][68];     // [k][q]
    __shared__ float Vs[64][68];     // [k][d]
    int tid = threadIdx.x;
    int tr = (tid >> 4) * 4;
    int tc = (tid & 15) * 4;
    float acc[4][4] = {};

    const float* prow = att + ((size_t)bh * SEQ + qt * 64) * SEQ;

    for (int kt = 0; kt <= qt; kt++) {
        #pragma unroll
        for (int it = 0; it < 4; it++) {
            int lin = tid + 256 * it;
            int r = lin >> 4;            // 0..63
            int c = (lin & 15) * 4;      // 0..60
            float4 pv = *(const float4*)(prow + (size_t)r * SEQ + kt * 64 + c);
            Pt[c + 0][r] = pv.x; Pt[c + 1][r] = pv.y;
            Pt[c + 2][r] = pv.z; Pt[c + 3][r] = pv.w;
            float4 vv = *(const float4*)(qkv + (size_t)(b * SEQ + kt * 64 + r) * E3
                                         + 2 * EMB + h * DHEAD + c);
            *(float4*)&Vs[r][c] = vv;
        }
        __syncthreads();
        #pragma unroll
        for (int k = 0; k < 64; k++) {
            float4 pa = *(const float4*)&Pt[k][tr];
            float4 vb = *(const float4*)&Vs[k][tc];
            float ra[4] = {pa.x, pa.y, pa.z, pa.w};
            float rb[4] = {vb.x, vb.y, vb.z, vb.w};
            #pragma unroll
            for (int i = 0; i < 4; i++)
                #pragma unroll
                for (int j = 0; j < 4; j++)
                    acc[i][j] += ra[i] * rb[j];
        }
        __syncthreads();
    }

    #pragma unroll
    for (int i = 0; i < 4; i++)
        #pragma unroll
        for (int j = 0; j < 4; j++)
            y[(size_t)(b * SEQ + qt * 64 + tr + i) * EMB + h * DHEAD + tc + j] = acc[i][j];
}

// ---------------- launch ----------------
extern "C" void kernel_launch(void* const* d_in, const int* in_sizes, int n_in,
                              void* d_out, int out_size)
{
    const int*   x    = (const int*)  d_in[0];
    const float* wte  = (const float*)d_in[1];
    const float* wpe  = (const float*)d_in[2];
    const float* ln1g = (const float*)d_in[3];
    const float* ln1b = (const float*)d_in[4];
    const float* attw = (const float*)d_in[5];
    const float* attb = (const float*)d_in[6];
    const float* apw  = (const float*)d_in[7];
    const float* apb  = (const float*)d_in[8];
    const float* ln2g = (const float*)d_in[9];
    const float* ln2b = (const float*)d_in[10];
    const float* fcw  = (const float*)d_in[11];
    const float* fcb  = (const float*)d_in[12];
    const float* fpw  = (const float*)d_in[13];
    const float* fpb  = (const float*)d_in[14];
    const float* lnfg = (const float*)d_in[15];
    const float* lnfb = (const float*)d_in[16];
    const float* lmw  = (const float*)d_in[17];
    float* out = (float*)d_out;

    float *h, *a, *yb, *qkv, *att, *fc;
    cudaGetSymbolAddress((void**)&h,   g_h);
    cudaGetSymbolAddress((void**)&a,   g_a);
    cudaGetSymbolAddress((void**)&yb,  g_y);
    cudaGetSymbolAddress((void**)&qkv, g_qkv);
    cudaGetSymbolAddress((void**)&att, g_att);
    cudaGetSymbolAddress((void**)&fc,  g_fc);

    embed_kernel<<<(TOK * EMB + 255) / 256, 256>>>(x, wte, wpe, h);

    for (int l = 0; l < LAYERS; l++) {
        ln_kernel<<<TOK, 256>>>(h, ln1g + l * EMB, ln1b + l * EMB, a);
        sgemm_kernel<0><<<dim3(E3 / 128, TOK / 128), 256>>>(
            a, attw + (size_t)l * EMB * E3, attb + (size_t)l * E3, qkv, TOK, E3, EMB);

        qk_kernel<<<dim3(SEQ / 64, SEQ / 64, BATCH * HEADS), 256>>>(qkv, att);
        softmax_kernel<<<dim3(SEQ, BATCH * HEADS), 256>>>(att);
        av_kernel<<<dim3(SEQ / 64, BATCH * HEADS), 256>>>(att, qkv, yb);

        sgemm_kernel<2><<<dim3(EMB / 128, TOK / 128), 256>>>(
            yb, apw + (size_t)l * EMB * EMB, apb + (size_t)l * EMB, h, TOK, EMB, EMB);

        ln_kernel<<<TOK, 256>>>(h, ln2g + l * EMB, ln2b + l * EMB, a);
        sgemm_kernel<1><<<dim3(E4 / 128, TOK / 128), 256>>>(
            a, fcw + (size_t)l * EMB * E4, fcb + (size_t)l * E4, fc, TOK, E4, EMB);
        sgemm_kernel<2><<<dim3(EMB / 128, TOK / 128), 256>>>(
            fc, fpw + (size_t)l * E4 * EMB, fpb + (size_t)l * EMB, h, TOK, EMB, E4);
    }

    ln_kernel<<<TOK, 256>>>(h, lnfg, lnfb, a);
    sgemm_kernel<0><<<dim3((VOCAB + 127) / 128, TOK / 128), 256>>>(
        a, lmw, nullptr, out, TOK, VOCAB, EMB);
}

// round 7
// speedup vs baseline: 2.0008x; 2.0008x over previous
#include <cuda_runtime.h>
#include <cuda_bf16.h>
#include <math.h>

// ---------------- constants ----------------
#define LAYERS 12
#define HEADS  12
#define EMB    768
#define DHEAD  64
#define VOCAB  50257
#define BATCH  4
#define SEQ    1024
#define TOK    (BATCH * SEQ)          // 4096
#define E3     (3 * EMB)              // 2304
#define E4     (4 * EMB)              // 3072

// ---------------- scratch (__device__ globals: no cudaMalloc allowed) ------
__device__ float g_h  [(size_t)TOK * EMB];            // residual stream
__device__ float g_a  [(size_t)TOK * EMB];            // layernorm output
__device__ float g_y  [(size_t)TOK * EMB];            // attention output
__device__ float g_qkv[(size_t)TOK * E3];             // qkv projections
__device__ float g_att[(size_t)BATCH * HEADS * SEQ * SEQ]; // attn probs
__device__ float g_fc [(size_t)TOK * E4];             // MLP hidden

// ---------------- helpers ----------------
__device__ __forceinline__ float gelu_f(float x) {
    float x3 = x * x * x;
    return 0.5f * x * (1.0f + tanhf(0.7978845608028654f * (x + 0.044715f * x3)));
}

__device__ __forceinline__ unsigned f2tf32(float x) {
    unsigned r;
    asm("cvt.rna.tf32.f32 %0, %1;" : "=r"(r) : "f"(x));
    return r;
}

// D += A*B  (m16n8k8 tf32, row.col)
__device__ __forceinline__ void mma_tf32(float* c, const unsigned* a, const unsigned* b) {
    asm volatile(
        "mma.sync.aligned.m16n8k8.row.col.f32.tf32.tf32.f32 "
        "{%0,%1,%2,%3}, {%4,%5,%6,%7}, {%8,%9}, {%0,%1,%2,%3};\n"
        : "+f"(c[0]), "+f"(c[1]), "+f"(c[2]), "+f"(c[3])
        : "r"(a[0]), "r"(a[1]), "r"(a[2]), "r"(a[3]),
          "r"(b[0]), "r"(b[1]));
}

__device__ __forceinline__ float warp_sum(float v) {
    #pragma unroll
    for (int o = 16; o > 0; o >>= 1) v += __shfl_xor_sync(0xffffffffu, v, o);
    return v;
}
__device__ __forceinline__ float warp_max(float v) {
    #pragma unroll
    for (int o = 16; o > 0; o >>= 1) v = fmaxf(v, __shfl_xor_sync(0xffffffffu, v, o));
    return v;
}
// block-wide reductions for 256 threads (8 warps); sm must hold >=8 floats
__device__ __forceinline__ float block_sum(float v, float* sm) {
    v = warp_sum(v);
    int w = threadIdx.x >> 5, l = threadIdx.x & 31;
    if (l == 0) sm[w] = v;
    __syncthreads();
    float r = (l < 8) ? sm[l] : 0.0f;
    r = warp_sum(r);
    __syncthreads();
    return r;
}
__device__ __forceinline__ float block_max(float v, float* sm) {
    v = warp_max(v);
    int w = threadIdx.x >> 5, l = threadIdx.x & 31;
    if (l == 0) sm[w] = v;
    __syncthreads();
    float r = (l < 8) ? sm[l] : -3.0e38f;
    r = warp_max(r);
    __syncthreads();
    return r;
}

// ---------------- embedding ----------------
__global__ __launch_bounds__(256) void embed_kernel(
    const int* __restrict__ x, const float* __restrict__ wte,
    const float* __restrict__ wpe, float* __restrict__ h)
{
    int i = blockIdx.x * 256 + threadIdx.x;
    if (i < TOK * EMB) {
        int t = i / EMB;
        int e = i - t * EMB;
        int s = t & (SEQ - 1);
        h[i] = wte[(size_t)x[t] * EMB + e] + wpe[(size_t)s * EMB + e];
    }
}

// ---------------- layernorm (row = 768) ----------------
__global__ __launch_bounds__(256) void ln_kernel(
    const float* __restrict__ x, const float* __restrict__ g,
    const float* __restrict__ b, float* __restrict__ y)
{
    __shared__ float red[8];
    int row = blockIdx.x;
    const float* xr = x + (size_t)row * EMB;
    int tid = threadIdx.x;
    float v0 = xr[tid], v1 = xr[tid + 256], v2 = xr[tid + 512];
    float s  = v0 + v1 + v2;
    float s2 = v0 * v0 + v1 * v1 + v2 * v2;
    s  = block_sum(s,  red);
    __syncthreads();
    s2 = block_sum(s2, red);
    float mean = s * (1.0f / EMB);
    float var  = s2 * (1.0f / EMB) - mean * mean;
    float inv  = rsqrtf(var + 1e-5f);
    float* yr = y + (size_t)row * EMB;
    yr[tid]       = (v0 - mean) * inv * g[tid]       + b[tid];
    yr[tid + 256] = (v1 - mean) * inv * g[tid + 256] + b[tid + 256];
    yr[tid + 512] = (v2 - mean) * inv * g[tid + 512] + b[tid + 512];
}

// ---------------- tensor-core GEMM: C[M,N] = A[M,K] @ B[K,N] (+bias) ------
// EPI: 0 = write, 1 = gelu then write, 2 = accumulate into C (residual)
// M % 128 == 0, K % 32 == 0. N may be ragged with odd stride (lm head).
// tf32 mma.sync m16n8k8. Block tile 128x128, k-tile 32. 8 warps as 4(m)x2(n);
// each warp computes 32x64 = 2 (m16) x 8 (n8) fragments.
// Bank-conflict layout:
//   As[m][k] stride 36  (36 % 32 == 4  -> frag reads hit 32 distinct banks)
//   Bs[k][n] stride 136 (136 % 32 == 8 -> frag reads conflict-free,
//                        tile writes contiguous)
template <int EPI>
__global__ __launch_bounds__(256) void mma_gemm_kernel(
    const float* __restrict__ A, const float* __restrict__ B,
    const float* __restrict__ bias, float* __restrict__ C,
    int M, int N, int K)
{
    __shared__ unsigned As[128][36];
    __shared__ unsigned Bs[32][136];

    int tid  = threadIdx.x;
    int lane = tid & 31;
    int wid  = tid >> 5;
    int g    = lane >> 2;      // 0..7
    int t4   = lane & 3;       // 0..3
    int wm   = (wid & 3) * 32; // warp m offset in block tile
    int wn   = (wid >> 2) * 64;// warp n offset in block tile

    int bm = blockIdx.y * 128;
    int bn = blockIdx.x * 128;

    float acc[2][8][4];
    #pragma unroll
    for (int mi = 0; mi < 2; mi++)
        #pragma unroll
        for (int nj = 0; nj < 8; nj++)
            #pragma unroll
            for (int e = 0; e < 4; e++) acc[mi][nj][e] = 0.0f;

    // vectorized B loads require fully in-bounds block AND 16B-aligned rows
    bool bvec = ((bn + 128) <= N) && ((N & 3) == 0);

    for (int k0 = 0; k0 < K; k0 += 32) {
        // ---- A tile: 128 rows x 32 k (coalesced float4 along k) ----
        #pragma unroll
        for (int i = 0; i < 4; i++) {
            int idx = tid + 256 * i;      // 0..1023
            int r = idx >> 3;             // 0..127
            int c = (idx & 7) * 4;        // 0..28
            float4 v = *(const float4*)(A + (size_t)(bm + r) * K + k0 + c);
            uint4 u;
            u.x = f2tf32(v.x); u.y = f2tf32(v.y);
            u.z = f2tf32(v.z); u.w = f2tf32(v.w);
            *(uint4*)&As[r][c] = u;
        }
        // ---- B tile: 32 k-rows x 128 n (coalesced along n) ----
        #pragma unroll
        for (int i = 0; i < 4; i++) {
            int idx = tid + 256 * i;      // 0..1023
            int kr = idx >> 5;            // 0..31
            int c  = (idx & 31) * 4;      // 0..124
            if (bvec) {
                float4 v = *(const float4*)(B + (size_t)(k0 + kr) * N + bn + c);
                uint4 u;
                u.x = f2tf32(v.x); u.y = f2tf32(v.y);
                u.z = f2tf32(v.z); u.w = f2tf32(v.w);
                *(uint4*)&Bs[kr][c] = u;
            } else {
                const float* Brow = B + (size_t)(k0 + kr) * N;
                #pragma unroll
                for (int j = 0; j < 4; j++) {
                    int n = bn + c + j;
                    Bs[kr][c + j] = f2tf32((n < N) ? Brow[n] : 0.0f);
                }
            }
        }
        __syncthreads();

        #pragma unroll
        for (int ks = 0; ks < 4; ks++) {
            int kk = ks * 8;
            unsigned af[2][4];
            #pragma unroll
            for (int mi = 0; mi < 2; mi++) {
                int m = wm + mi * 16 + g;
                af[mi][0] = As[m    ][kk + t4];
                af[mi][1] = As[m + 8][kk + t4];
                af[mi][2] = As[m    ][kk + t4 + 4];
                af[mi][3] = As[m + 8][kk + t4 + 4];
            }
            #pragma unroll
            for (int nj = 0; nj < 8; nj++) {
                unsigned bf[2];
                int n = wn + nj * 8 + g;
                bf[0] = Bs[kk + t4    ][n];
                bf[1] = Bs[kk + t4 + 4][n];
                mma_tf32(acc[0][nj], af[0], bf);
                mma_tf32(acc[1][nj], af[1], bf);
            }
        }
        __syncthreads();
    }

    // ---- epilogue ----
    // fragment C layout: c0:(g, 2*t4) c1:(g, 2*t4+1) c2:(g+8, 2*t4) c3:(g+8, 2*t4+1)
    #pragma unroll
    for (int mi = 0; mi < 2; mi++) {
        int r = bm + wm + mi * 16 + g;
        #pragma unroll
        for (int nj = 0; nj < 8; nj++) {
            int cb = bn + wn + nj * 8 + 2 * t4;
            #pragma unroll
            for (int e = 0; e < 4; e++) {
                int row = r + (e >> 1) * 8;
                int col = cb + (e & 1);
                if (col < N) {
                    float v = acc[mi][nj][e];
                    if (bias) v += bias[col];
                    size_t idx = (size_t)row * N + col;
                    if (EPI == 1) v = gelu_f(v);
                    if (EPI == 2) v += C[idx];
                    C[idx] = v;
                }
            }
        }
    }
}

// ---------------- attention: scores = Q K^T * scale (64x64 tiles) --------
__global__ __launch_bounds__(256) void qk_kernel(
    const float* __restrict__ qkv, float* __restrict__ att)
{
    int kt = blockIdx.x, qt = blockIdx.y, bh = blockIdx.z;
    if (kt > qt) return;             // fully-masked tile
    int b = bh / HEADS, h = bh - b * HEADS;

    __shared__ float Qt[64][68];     // [d][q]
    __shared__ float Kt[64][68];     // [d][k]
    int tid = threadIdx.x;

    const float* qb = qkv + (size_t)(b * SEQ + qt * 64) * E3 + h * DHEAD;
    const float* kb = qkv + (size_t)(b * SEQ + kt * 64) * E3 + EMB + h * DHEAD;

    #pragma unroll
    for (int it = 0; it < 4; it++) {
        int lin = tid + 256 * it;    // 0..1023
        int r = lin >> 4;            // 0..63
        int d = (lin & 15) * 4;
        float4 qv = *(const float4*)(qb + (size_t)r * E3 + d);
        Qt[d + 0][r] = qv.x; Qt[d + 1][r] = qv.y;
        Qt[d + 2][r] = qv.z; Qt[d + 3][r] = qv.w;
        float4 kv = *(const float4*)(kb + (size_t)r * E3 + d);
        Kt[d + 0][r] = kv.x; Kt[d + 1][r] = kv.y;
        Kt[d + 2][r] = kv.z; Kt[d + 3][r] = kv.w;
    }
    __syncthreads();

    int tr = (tid >> 4) * 4;
    int tc = (tid & 15) * 4;
    float acc[4][4] = {};
    #pragma unroll
    for (int d = 0; d < 64; d++) {
        float4 qa = *(const float4*)&Qt[d][tr];
        float4 kk = *(const float4*)&Kt[d][tc];
        float ra[4] = {qa.x, qa.y, qa.z, qa.w};
        float rb[4] = {kk.x, kk.y, kk.z, kk.w};
        #pragma unroll
        for (int i = 0; i < 4; i++)
            #pragma unroll
            for (int j = 0; j < 4; j++)
                acc[i][j] += ra[i] * rb[j];
    }

    const float scale = 0.125f;      // 1/sqrt(64)
    float* out = att + ((size_t)bh * SEQ + qt * 64) * SEQ + kt * 64;
    #pragma unroll
    for (int i = 0; i < 4; i++)
        #pragma unroll
        for (int j = 0; j < 4; j++)
            out[(size_t)(tr + i) * SEQ + tc + j] = acc[i][j] * scale;
}

// ---------------- causal row softmax ----------------
__global__ __launch_bounds__(256) void softmax_kernel(float* __restrict__ att)
{
    __shared__ float red[8];
    int q = blockIdx.x, bh = blockIdx.y;
    float* row = att + ((size_t)bh * SEQ + q) * SEQ;
    int n = q + 1;
    int tid = threadIdx.x;

    float m = -3.0e38f;
    for (int j = tid; j < n; j += 256) m = fmaxf(m, row[j]);
    m = block_max(m, red);

    float s = 0.0f;
    for (int j = tid; j < n; j += 256) {
        float e = __expf(row[j] - m);
        row[j] = e;
        s += e;
    }
    s = block_sum(s, red);
    float inv = 1.0f / s;

    for (int j = tid; j < SEQ; j += 256)
        row[j] = (j < n) ? row[j] * inv : 0.0f;
}

// ---------------- attention: Y = P @ V (64x64 tiles over k) --------------
__global__ __launch_bounds__(256) void av_kernel(
    const float* __restrict__ att, const float* __restrict__ qkv,
    float* __restrict__ y)
{
    int qt = blockIdx.x, bh = blockIdx.y;
    int b = bh / HEADS, h = bh - b * HEADS;

    __shared__ float Pt[64][68];     // [k][q]
    __shared__ float Vs[64][68];     // [k][d]
    int tid = threadIdx.x;
    int tr = (tid >> 4) * 4;
    int tc = (tid & 15) * 4;
    float acc[4][4] = {};

    const float* prow = att + ((size_t)bh * SEQ + qt * 64) * SEQ;

    for (int kt = 0; kt <= qt; kt++) {
        #pragma unroll
        for (int it = 0; it < 4; it++) {
            int lin = tid + 256 * it;
            int r = lin >> 4;            // 0..63
            int c = (lin & 15) * 4;      // 0..60
            float4 pv = *(const float4*)(prow + (size_t)r * SEQ + kt * 64 + c);
            Pt[c + 0][r] = pv.x; Pt[c + 1][r] = pv.y;
            Pt[c + 2][r] = pv.z; Pt[c + 3][r] = pv.w;
            float4 vv = *(const float4*)(qkv + (size_t)(b * SEQ + kt * 64 + r) * E3
                                         + 2 * EMB + h * DHEAD + c);
            *(float4*)&Vs[r][c] = vv;
        }
        __syncthreads();
        #pragma unroll
        for (int k = 0; k < 64; k++) {
            float4 pa = *(const float4*)&Pt[k][tr];
            float4 vb = *(const float4*)&Vs[k][tc];
            float ra[4] = {pa.x, pa.y, pa.z, pa.w};
            float rb[4] = {vb.x, vb.y, vb.z, vb.w};
            #pragma unroll
            for (int i = 0; i < 4; i++)
                #pragma unroll
                for (int j = 0; j < 4; j++)
                    acc[i][j] += ra[i] * rb[j];
        }
        __syncthreads();
    }

    #pragma unroll
    for (int i = 0; i < 4; i++)
        #pragma unroll
        for (int j = 0; j < 4; j++)
            y[(size_t)(b * SEQ + qt * 64 + tr + i) * EMB + h * DHEAD + tc + j] = acc[i][j];
}

// ---------------- launch ----------------
extern "C" void kernel_launch(void* const* d_in, const int* in_sizes, int n_in,
                              void* d_out, int out_size)
{
    const int*   x    = (const int*)  d_in[0];
    const float* wte  = (const float*)d_in[1];
    const float* wpe  = (const float*)d_in[2];
    const float* ln1g = (const float*)d_in[3];
    const float* ln1b = (const float*)d_in[4];
    const float* attw = (const float*)d_in[5];
    const float* attb = (const float*)d_in[6];
    const float* apw  = (const float*)d_in[7];
    const float* apb  = (const float*)d_in[8];
    const float* ln2g = (const float*)d_in[9];
    const float* ln2b = (const float*)d_in[10];
    const float* fcw  = (const float*)d_in[11];
    const float* fcb  = (const float*)d_in[12];
    const float* fpw  = (const float*)d_in[13];
    const float* fpb  = (const float*)d_in[14];
    const float* lnfg = (const float*)d_in[15];
    const float* lnfb = (const float*)d_in[16];
    const float* lmw  = (const float*)d_in[17];
    float* out = (float*)d_out;

    float *h, *a, *yb, *qkv, *att, *fc;
    cudaGetSymbolAddress((void**)&h,   g_h);
    cudaGetSymbolAddress((void**)&a,   g_a);
    cudaGetSymbolAddress((void**)&yb,  g_y);
    cudaGetSymbolAddress((void**)&qkv, g_qkv);
    cudaGetSymbolAddress((void**)&att, g_att);
    cudaGetSymbolAddress((void**)&fc,  g_fc);

    embed_kernel<<<(TOK * EMB + 255) / 256, 256>>>(x, wte, wpe, h);

    for (int l = 0; l < LAYERS; l++) {
        ln_kernel<<<TOK, 256>>>(h, ln1g + l * EMB, ln1b + l * EMB, a);
        mma_gemm_kernel<0><<<dim3(E3 / 128, TOK / 128), 256>>>(
            a, attw + (size_t)l * EMB * E3, attb + (size_t)l * E3, qkv, TOK, E3, EMB);

        qk_kernel<<<dim3(SEQ / 64, SEQ / 64, BATCH * HEADS), 256>>>(qkv, att);
        softmax_kernel<<<dim3(SEQ, BATCH * HEADS), 256>>>(att);
        av_kernel<<<dim3(SEQ / 64, BATCH * HEADS), 256>>>(att, qkv, yb);

        mma_gemm_kernel<2><<<dim3(EMB / 128, TOK / 128), 256>>>(
            yb, apw + (size_t)l * EMB * EMB, apb + (size_t)l * EMB, h, TOK, EMB, EMB);

        ln_kernel<<<TOK, 256>>>(h, ln2g + l * EMB, ln2b + l * EMB, a);
        mma_gemm_kernel<1><<<dim3(E4 / 128, TOK / 128), 256>>>(
            a, fcw + (size_t)l * EMB * E4, fcb + (size_t)l * E4, fc, TOK, E4, EMB);
        mma_gemm_kernel<2><<<dim3(EMB / 128, TOK / 128), 256>>>(
            fc, fpw + (size_t)l * E4 * EMB, fpb + (size_t)l * EMB, h, TOK, EMB, E4);
    }

    ln_kernel<<<TOK, 256>>>(h, lnfg, lnfb, a);
    mma_gemm_kernel<0><<<dim3((VOCAB + 127) / 128, TOK / 128), 256>>>(
        a, lmw, nullptr, out, TOK, VOCAB, EMB);
}